// round 1
// baseline (speedup 1.0000x reference)
#include <cuda_runtime.h>
#include <math.h>

// ---------------- device scratch (no allocations allowed) ----------------
__device__ float g_scores[256 * 256];
__device__ int   g_idxL[256];
__device__ int   g_idxR[256];
__device__ float g_xent[6144];
__device__ float g_pu[8 * 6144];
__device__ float g_pv[8 * 6144];

// =====================================================================
// Kernel A: fused score GEMM.
// For each pair (l, r): x = |L_l - R_r| (length 768)
//   u = x @ Wn + bn ; v = x @ Wg + bg
//   score = sum_j ( relu(u_j)*sig(v_j) + (1-sig(v_j))*x_j ) * Wl_j
// Block = 64 pairs (one l, 64 consecutive r). Loop j in tiles of 64,
// inner K loop over 768 in tiles of 16. Two GEMMs (Wn, Wg) share A.
// =====================================================================
#define BM 64
#define BN 64
#define BK 16

__global__ __launch_bounds__(256) void score_kernel(
    const float* __restrict__ L, const float* __restrict__ R,
    const float* __restrict__ Wn, const float* __restrict__ bn,
    const float* __restrict__ Wg, const float* __restrict__ bg,
    const float* __restrict__ Wl)
{
    __shared__ float sA[BK][BM];
    __shared__ float sN[BK][BN];
    __shared__ float sG[BK][BN];
    __shared__ float sRed[BM][17];

    const int b  = blockIdx.x;        // 0..1023
    const int l  = b >> 2;            // each l covered by 4 blocks
    const int r0 = (b & 3) * 64;
    const int t  = threadIdx.x;       // 256 threads, 16x16
    const int ty = t >> 4, tx = t & 15;
    const int tm0 = ty * 4, tj0 = tx * 4;

    float accS[4] = {0.f, 0.f, 0.f, 0.f};

    for (int jt = 0; jt < 12; ++jt) {
        const int j0 = jt * BN;
        float accU[4][4] = {};
        float accV[4][4] = {};

        for (int kt = 0; kt < 48; ++kt) {
            const int k0 = kt * BK;
            __syncthreads();
            // --- load A tile: sA[k][m] = |L[l,k0+k] - R[r0+m,k0+k]| ---
            {
                const int m  = t >> 2;
                const int kq = (t & 3) * 4;
                const float4 rv = *(const float4*)(R + (size_t)(r0 + m) * 768 + k0 + kq);
                const float4 lv = *(const float4*)(L + (size_t)l * 768 + k0 + kq);
                sA[kq + 0][m] = fabsf(lv.x - rv.x);
                sA[kq + 1][m] = fabsf(lv.y - rv.y);
                sA[kq + 2][m] = fabsf(lv.z - rv.z);
                sA[kq + 3][m] = fabsf(lv.w - rv.w);
            }
            // --- load weight tiles ---
            {
                const int k = t >> 4;          // 0..15
                const int j = (t & 15) * 4;    // 0..60
                *(float4*)&sN[k][j] = *(const float4*)(Wn + (size_t)(k0 + k) * 768 + j0 + j);
                *(float4*)&sG[k][j] = *(const float4*)(Wg + (size_t)(k0 + k) * 768 + j0 + j);
            }
            __syncthreads();

            #pragma unroll
            for (int k = 0; k < BK; ++k) {
                float a[4], wn[4], wg[4];
                *(float4*)a  = *(const float4*)&sA[k][tm0];
                *(float4*)wn = *(const float4*)&sN[k][tj0];
                *(float4*)wg = *(const float4*)&sG[k][tj0];
                #pragma unroll
                for (int mi = 0; mi < 4; ++mi) {
                    #pragma unroll
                    for (int ji = 0; ji < 4; ++ji) {
                        accU[mi][ji] = fmaf(a[mi], wn[ji], accU[mi][ji]);
                        accV[mi][ji] = fmaf(a[mi], wg[ji], accV[mi][ji]);
                    }
                }
            }
        }

        // --- epilogue for this j tile ---
        #pragma unroll
        for (int ji = 0; ji < 4; ++ji) {
            const int j = j0 + tj0 + ji;
            const float bnj = bn[j];
            const float bgj = bg[j];
            const float wlj = Wl[j];
            const float Lj  = L[(size_t)l * 768 + j];
            #pragma unroll
            for (int mi = 0; mi < 4; ++mi) {
                const int rr = r0 + tm0 + mi;
                const float x = fabsf(Lj - R[(size_t)rr * 768 + j]);
                const float u = accU[mi][ji] + bnj;
                const float v = accV[mi][ji] + bgj;
                const float g = 1.f / (1.f + __expf(-v));
                const float h = fmaxf(u, 0.f);
                accS[mi] += (h * g + (1.f - g) * x) * wlj;
            }
        }
    }

    // --- reduce partial scores across tx ---
    __syncthreads();
    #pragma unroll
    for (int mi = 0; mi < 4; ++mi) sRed[tm0 + mi][tx] = accS[mi];
    __syncthreads();
    if (t < 64) {
        float s = 0.f;
        #pragma unroll
        for (int i = 0; i < 16; ++i) s += sRed[t][i];
        g_scores[l * 256 + r0 + t] = s;
    }
}

// =====================================================================
// Kernel B: argmax over rows (idxL) and columns (idxR), ties -> lowest idx
// =====================================================================
__global__ __launch_bounds__(256) void argmax_kernel()
{
    const int b = blockIdx.x;   // 0..511
    const int t = threadIdx.x;
    const bool col = (b >= 256);
    const int idx = col ? (b - 256) : b;

    float v = col ? g_scores[t * 256 + idx] : g_scores[idx * 256 + t];
    __shared__ float sv[256];
    __shared__ int   si[256];
    sv[t] = v; si[t] = t;
    __syncthreads();
    for (int s = 128; s > 0; s >>= 1) {
        if (t < s) {
            if (sv[t + s] > sv[t] || (sv[t + s] == sv[t] && si[t + s] < si[t])) {
                sv[t] = sv[t + s]; si[t] = si[t + s];
            }
        }
        __syncthreads();
    }
    if (t == 0) {
        if (col) g_idxR[idx] = si[0];
        else     g_idxL[idx] = si[0];
    }
}

// =====================================================================
// Kernel C: ragged attribute matching. One block per (side, attribute).
// =====================================================================
__global__ __launch_bounds__(256) void attr_kernel(
    const float* __restrict__ L, const float* __restrict__ R,
    const float* __restrict__ AEl, const float* __restrict__ AEr,
    const float* __restrict__ empty,
    const int* __restrict__ lensL, const int* __restrict__ lensR)
{
    const int b = blockIdx.x;      // 0..7
    const int side = b >> 2;       // 0 = left, 1 = right
    const int a = b & 3;
    const float* T  = side ? R : L;             // tokens
    const float* O  = side ? L : R;             // counterpart for cmp rows
    const int*   ix = side ? g_idxR : g_idxL;
    const float* AE = side ? AEr : AEl;
    const int* lens = side ? lensR : lensL;
    const int t = threadIdx.x;

    int start = 0;
    for (int i = 0; i < a; ++i) start += lens[i];
    const int len = lens[a];
    float* rep = g_xent + (size_t)(side * 4 + a) * 768;

    if (len == 0) {
        for (int d = t; d < 768; d += 256) rep[d] = empty[d];
        return;
    }

    __shared__ float sw[256];
    __shared__ float red[256];

    float s = -1e30f;
    if (t < len) {
        float acc = 0.f;
        const float* tok = T + (size_t)(start + t) * 768;
        const float* ae  = AE + (size_t)a * 768;
        for (int d = 0; d < 768; ++d) acc = fmaf(tok[d], ae[d], acc);
        s = acc;
    }
    red[t] = s;
    __syncthreads();
    for (int st = 128; st > 0; st >>= 1) {
        if (t < st) red[t] = fmaxf(red[t], red[t + st]);
        __syncthreads();
    }
    const float m = red[0];
    __syncthreads();
    const float e = (t < len) ? __expf(s - m) : 0.f;
    red[t] = e;
    __syncthreads();
    for (int st = 128; st > 0; st >>= 1) {
        if (t < st) red[t] += red[t + st];
        __syncthreads();
    }
    const float z = red[0];
    sw[t] = e / z;
    __syncthreads();

    for (int d = t; d < 768; d += 256) {
        float acc = 0.f;
        for (int i = 0; i < len; ++i) {
            const int tok = start + i;
            const float x = fabsf(T[(size_t)tok * 768 + d] - O[(size_t)ix[tok] * 768 + d]);
            acc = fmaf(sw[i], x, acc);
        }
        rep[d] = acc;
    }
}

// =====================================================================
// Kernel D: entity highway matvec partials. 302 MB streamed, HBM-bound.
// grid = (24 col-blocks of 256 cols, 8 row-splits of 768 rows)
// =====================================================================
__global__ __launch_bounds__(256) void ent_partial(
    const float* __restrict__ Wn, const float* __restrict__ Wg)
{
    const int j  = blockIdx.x * 256 + threadIdx.x;  // 0..6143
    const int rs = blockIdx.y;                      // 0..7
    const int i0 = rs * 768;
    float au = 0.f, av = 0.f;
    #pragma unroll 4
    for (int i = 0; i < 768; ++i) {
        const float xi = g_xent[i0 + i];
        au = fmaf(xi, Wn[(size_t)(i0 + i) * 6144 + j], au);
        av = fmaf(xi, Wg[(size_t)(i0 + i) * 6144 + j], av);
    }
    g_pu[rs * 6144 + j] = au;
    g_pv[rs * 6144 + j] = av;
}

// =====================================================================
// Kernel E: finalize entity highway + logits + softmax
// =====================================================================
__global__ __launch_bounds__(256) void ent_final(
    const float* __restrict__ bn, const float* __restrict__ bg,
    const float* __restrict__ Wl2, const float* __restrict__ bl2,
    float* __restrict__ out)
{
    const int t = threadIdx.x;
    float l0 = 0.f, l1 = 0.f;
    for (int j = t; j < 6144; j += 256) {
        float u = bn[j], v = bg[j];
        #pragma unroll
        for (int s = 0; s < 8; ++s) {
            u += g_pu[s * 6144 + j];
            v += g_pv[s * 6144 + j];
        }
        const float x = g_xent[j];
        const float g = 1.f / (1.f + __expf(-v));
        const float hw = fmaxf(u, 0.f) * g + (1.f - g) * x;
        l0 = fmaf(hw, Wl2[(size_t)j * 2 + 0], l0);
        l1 = fmaf(hw, Wl2[(size_t)j * 2 + 1], l1);
    }
    __shared__ float r0[256], r1[256];
    r0[t] = l0; r1[t] = l1;
    __syncthreads();
    for (int s = 128; s > 0; s >>= 1) {
        if (t < s) { r0[t] += r0[t + s]; r1[t] += r1[t + s]; }
        __syncthreads();
    }
    if (t == 0) {
        const float a = r0[0] + bl2[0];
        const float b = r1[0] + bl2[1];
        const float m = fmaxf(a, b);
        const float ea = __expf(a - m), eb = __expf(b - m);
        const float inv = 1.f / (ea + eb);
        out[0] = ea * inv;
        out[1] = eb * inv;
    }
}

// =====================================================================
extern "C" void kernel_launch(void* const* d_in, const int* in_sizes, int n_in,
                              void* d_out, int out_size)
{
    const float* left_emb   = (const float*)d_in[0];
    const float* right_emb  = (const float*)d_in[1];
    const float* Wn_tok     = (const float*)d_in[2];
    const float* bn_tok     = (const float*)d_in[3];
    const float* Wg_tok     = (const float*)d_in[4];
    const float* bg_tok     = (const float*)d_in[5];
    const float* W_lin_tok  = (const float*)d_in[6];
    // d_in[7] = b_lin_tok (constant offset, irrelevant for argmax)
    const float* attr_l     = (const float*)d_in[8];
    const float* attr_r     = (const float*)d_in[9];
    const float* Wn_ent     = (const float*)d_in[10];
    const float* bn_ent     = (const float*)d_in[11];
    const float* Wg_ent     = (const float*)d_in[12];
    const float* bg_ent     = (const float*)d_in[13];
    const float* W_lin_ent  = (const float*)d_in[14];
    const float* b_lin_ent  = (const float*)d_in[15];
    const float* empty_attr = (const float*)d_in[16];
    const int*   lensL      = (const int*)d_in[17];
    const int*   lensR      = (const int*)d_in[18];

    float* out = (float*)d_out;

    score_kernel<<<1024, 256>>>(left_emb, right_emb, Wn_tok, bn_tok,
                                Wg_tok, bg_tok, W_lin_tok);
    argmax_kernel<<<512, 256>>>();
    attr_kernel<<<8, 256>>>(left_emb, right_emb, attr_l, attr_r,
                            empty_attr, lensL, lensR);
    dim3 gridD(24, 8);
    ent_partial<<<gridD, 256>>>(Wn_ent, Wg_ent);
    ent_final<<<1, 256>>>(bn_ent, bg_ent, W_lin_ent, b_lin_ent, out);
}

// round 4
// speedup vs baseline: 1.8318x; 1.8318x over previous
#include <cuda_runtime.h>
#include <cuda_bf16.h>
#include <math.h>
#include <stdint.h>

// ============================ device scratch ============================
__device__ float g_scores[256 * 256];
__device__ int   g_idxL[256];
__device__ int   g_idxR[256];
__device__ float g_xent[6144];
__device__ float g_pu[32 * 6144];
__device__ float g_pv[32 * 6144];
// [tile(4: nH,nL,gH,gL)][jt(12)][kt(24)] tiles of 64j x 32k bf16 (4096B each)
__device__ __align__(16) __nv_bfloat16 g_Wprep[4 * 12 * 24 * 2048];

#define NJT 12
#define NKT 24
#define NIT (NJT * NKT)

// SMEM layout (bytes): A stages 2x32KB, W stages 2x16KB, meta 1KB, score 8KB
#define OFF_AHI(st) ((st) * 32768)
#define OFF_ALO(st) ((st) * 32768 + 16384)
#define OFF_WT(st)  (65536 + (st) * 16384)
#define OFF_META    98304
#define OFF_SC      99328
#define SMEM_BYTES  107520

// ============================ helpers ============================
__device__ __forceinline__ uint32_t smem_u32(const void* p) {
    uint32_t a;
    asm("{ .reg .u64 t; cvta.to.shared.u64 t, %1; cvt.u32.u64 %0, t; }" : "=r"(a) : "l"(p));
    return a;
}
__device__ __forceinline__ void cp16(uint32_t s, const void* g) {
    asm volatile("cp.async.cg.shared.global [%0], [%1], 16;" :: "r"(s), "l"(g));
}
__device__ __forceinline__ void cp_commit() { asm volatile("cp.async.commit_group;"); }
__device__ __forceinline__ void cp_wait0()  { asm volatile("cp.async.wait_group 0;" ::: "memory"); }
__device__ __forceinline__ void ldsm4(uint32_t& r0, uint32_t& r1, uint32_t& r2, uint32_t& r3,
                                      uint32_t a) {
    asm volatile("ldmatrix.sync.aligned.m8n8.x4.shared.b16 {%0,%1,%2,%3}, [%4];"
                 : "=r"(r0), "=r"(r1), "=r"(r2), "=r"(r3) : "r"(a));
}
__device__ __forceinline__ void mma16816(float* d, const uint32_t* a, const uint32_t* b) {
    asm volatile("mma.sync.aligned.m16n8k16.row.col.f32.bf16.bf16.f32 "
                 "{%0,%1,%2,%3},{%4,%5,%6,%7},{%8,%9},{%0,%1,%2,%3};"
                 : "+f"(d[0]), "+f"(d[1]), "+f"(d[2]), "+f"(d[3])
                 : "r"(a[0]), "r"(a[1]), "r"(a[2]), "r"(a[3]), "r"(b[0]), "r"(b[1]));
}
// RN split of float pair -> packed bf16x2 hi + lo (residual)
__device__ __forceinline__ void split2(float d0, float d1, uint32_t& hi, uint32_t& lo) {
    union { __nv_bfloat162 b; uint32_t u; } ch, cl;
    ch.b = __floats2bfloat162_rn(d0, d1);
    float f0 = __uint_as_float(ch.u << 16);
    float f1 = __uint_as_float(ch.u & 0xFFFF0000u);
    cl.b = __floats2bfloat162_rn(d0 - f0, d1 - f1);
    hi = ch.u; lo = cl.u;
}

// ============================ Kernel P: weight prep ============================
__global__ __launch_bounds__(256) void prep_w(const float* __restrict__ Wn,
                                              const float* __restrict__ Wg)
{
    int tid = blockIdx.x * 256 + threadIdx.x;      // 147456 = 2*96*768
    int mat = tid / 73728;
    int rem = tid - mat * 73728;
    int kc  = rem / 768;                           // k-chunk of 8
    int j   = rem - kc * 768;
    const float* W = mat ? Wg : Wn;
    int k0 = kc * 8;
    uint32_t hi[4], lo[4];
    #pragma unroll
    for (int p = 0; p < 4; ++p)
        split2(W[(size_t)(k0 + 2 * p) * 768 + j], W[(size_t)(k0 + 2 * p + 1) * 768 + j],
               hi[p], lo[p]);
    int kt = k0 >> 5;
    int c  = (k0 >> 3) & 3;
    int jt = j >> 6;
    int row = j & 63;
    int off = row * 64 + ((c ^ ((row >> 1) & 3)) << 4);
    char* bh = (char*)g_Wprep + (size_t)(((mat * 2 + 0) * NJT + jt) * NKT + kt) * 4096 + off;
    char* bl = (char*)g_Wprep + (size_t)(((mat * 2 + 1) * NJT + jt) * NKT + kt) * 4096 + off;
    *(uint4*)bh = make_uint4(hi[0], hi[1], hi[2], hi[3]);
    *(uint4*)bl = make_uint4(lo[0], lo[1], lo[2], lo[3]);
}

// ============================ Kernel A: HMMA score GEMM ============================
__device__ __forceinline__ void build_a(char* smem, const float* __restrict__ Rg,
                                        const float* __restrict__ Lrow,
                                        int kt, int st, int t)
{
    const float* Rr = Rg + (size_t)t * 768 + kt * 32;
    const float* Lr = Lrow + kt * 32;
    char* hb = smem + OFF_AHI(st);
    char* lb = smem + OFF_ALO(st);
    #pragma unroll
    for (int c = 0; c < 4; ++c) {
        float4 r0 = *(const float4*)(Rr + c * 8);
        float4 r1 = *(const float4*)(Rr + c * 8 + 4);
        float4 l0 = *(const float4*)(Lr + c * 8);
        float4 l1 = *(const float4*)(Lr + c * 8 + 4);
        uint32_t h0, h1, h2, h3, e0, e1, e2, e3;
        split2(fabsf(l0.x - r0.x), fabsf(l0.y - r0.y), h0, e0);
        split2(fabsf(l0.z - r0.z), fabsf(l0.w - r0.w), h1, e1);
        split2(fabsf(l1.x - r1.x), fabsf(l1.y - r1.y), h2, e2);
        split2(fabsf(l1.z - r1.z), fabsf(l1.w - r1.w), h3, e3);
        int off = t * 64 + ((c ^ ((t >> 1) & 3)) << 4);
        *(uint4*)(hb + off) = make_uint4(h0, h1, h2, h3);
        *(uint4*)(lb + off) = make_uint4(e0, e1, e2, e3);
    }
}
__device__ __forceinline__ void copy_w(uint32_t sb, int jt, int kt, int st, int t)
{
    #pragma unroll
    for (int q = 0; q < 4; ++q)
        cp16(sb + OFF_WT(st) + q * 4096 + t * 16,
             (const char*)g_Wprep + (size_t)((q * NJT + jt) * NKT + kt) * 4096 + t * 16);
}

__global__ __launch_bounds__(256, 1) void score_kernel(
    const float* __restrict__ L, const float* __restrict__ R,
    const float* __restrict__ bn, const float* __restrict__ bg,
    const float* __restrict__ Wl)
{
    extern __shared__ __align__(1024) char smem[];
    const uint32_t sb = smem_u32(smem);
    const int t = threadIdx.x;
    const int lane = t & 31;
    const int wm = (t >> 5) >> 1, wn = (t >> 5) & 1;   // 4m x 2n warp grid
    const int bl = blockIdx.x;                          // = l
    const float* Lrow = L + (size_t)bl * 768;

    copy_w(sb, 0, 0, 0, t);
    cp_commit();
    build_a(smem, R, Lrow, 0, 0, t);
    cp_wait0();
    __syncthreads();

    float scoreAcc[4][2] = {};

    for (int jt = 0; jt < NJT; ++jt) {
        float Uacc[4][4][4] = {};
        float Vacc[4][4][4] = {};
        if (t < 64) {
            float* sm = (float*)(smem + OFF_META);
            int j = jt * 64 + t;
            sm[t] = bn[j]; sm[64 + t] = bg[j]; sm[128 + t] = Wl[j]; sm[192 + t] = Lrow[j];
        }
        for (int kt = 0; kt < NKT; ++kt) {
            const int i = jt * NKT + kt;
            const int st = i & 1;
            if (i + 1 < NIT) {
                const int jn = (kt == NKT - 1) ? jt + 1 : jt;
                const int kn = (kt == NKT - 1) ? 0 : kt + 1;
                copy_w(sb, jn, kn, st ^ 1, t);
                cp_commit();
                build_a(smem, R, Lrow, kn, st ^ 1, t);
            }
            #pragma unroll
            for (int s = 0; s < 2; ++s) {
                uint32_t B[4][4][2];
                #pragma unroll
                for (int q = 0; q < 4; ++q) {
                    #pragma unroll
                    for (int h = 0; h < 2; ++h) {
                        int row = wn * 32 + h * 16 + ((lane >> 4) & 1) * 8 + (lane & 7);
                        int chunk = s * 2 + ((lane >> 3) & 1);
                        uint32_t addr = sb + OFF_WT(st) + q * 4096 +
                                        row * 64 + ((chunk ^ ((row >> 1) & 3)) << 4);
                        ldsm4(B[q][2 * h][0], B[q][2 * h][1],
                              B[q][2 * h + 1][0], B[q][2 * h + 1][1], addr);
                    }
                }
                #pragma unroll
                for (int mt = 0; mt < 4; ++mt) {
                    uint32_t A[4];
                    int row = wm * 64 + mt * 16 + ((lane >> 3) & 1) * 8 + (lane & 7);
                    int chunk = s * 2 + ((lane >> 4) & 1);
                    uint32_t swz = row * 64 + ((chunk ^ ((row >> 1) & 3)) << 4);
                    ldsm4(A[0], A[1], A[2], A[3], sb + OFF_AHI(st) + swz);
                    #pragma unroll
                    for (int nt = 0; nt < 4; ++nt) {
                        mma16816(Uacc[mt][nt], A, B[0][nt]);
                        mma16816(Uacc[mt][nt], A, B[1][nt]);
                        mma16816(Vacc[mt][nt], A, B[2][nt]);
                        mma16816(Vacc[mt][nt], A, B[3][nt]);
                    }
                    ldsm4(A[0], A[1], A[2], A[3], sb + OFF_ALO(st) + swz);
                    #pragma unroll
                    for (int nt = 0; nt < 4; ++nt) {
                        mma16816(Uacc[mt][nt], A, B[0][nt]);
                        mma16816(Vacc[mt][nt], A, B[2][nt]);
                    }
                }
            }
            if (kt == NKT - 1) {
                const float* smf = (const float*)(smem + OFF_META);
                #pragma unroll
                for (int mt = 0; mt < 4; ++mt) {
                    #pragma unroll
                    for (int hf = 0; hf < 2; ++hf) {
                        const int r = wm * 64 + mt * 16 + hf * 8 + (lane >> 2);
                        const float* Rr = R + (size_t)r * 768 + jt * 64;
                        float sc = scoreAcc[mt][hf];
                        #pragma unroll
                        for (int nt = 0; nt < 4; ++nt) {
                            #pragma unroll
                            for (int e = 0; e < 2; ++e) {
                                const int jl = wn * 32 + nt * 8 + ((lane & 3) << 1) + e;
                                const float x = fabsf(smf[192 + jl] - Rr[jl]);
                                const float u = Uacc[mt][nt][hf * 2 + e] + smf[jl];
                                const float v = Vacc[mt][nt][hf * 2 + e] + smf[64 + jl];
                                const float g = 1.f / (1.f + __expf(-v));
                                sc += (fmaxf(u, 0.f) * g + (1.f - g) * x) * smf[128 + jl];
                            }
                        }
                        scoreAcc[mt][hf] = sc;
                    }
                }
            }
            cp_wait0();
            __syncthreads();
        }
    }

    float* sS = (float*)(smem + OFF_SC);
    #pragma unroll
    for (int mt = 0; mt < 4; ++mt)
        #pragma unroll
        for (int hf = 0; hf < 2; ++hf)
            sS[(wm * 64 + mt * 16 + hf * 8 + (lane >> 2)) * 8 + wn * 4 + (lane & 3)] =
                scoreAcc[mt][hf];
    __syncthreads();
    float s = 0.f;
    #pragma unroll
    for (int q = 0; q < 8; ++q) s += sS[t * 8 + q];
    g_scores[bl * 256 + t] = s;
}

// ============================ Kernel B: argmax ============================
__global__ __launch_bounds__(256) void argmax_kernel()
{
    const int b = blockIdx.x;
    const int t = threadIdx.x;
    const bool col = (b >= 256);
    const int idx = col ? (b - 256) : b;
    float v = col ? g_scores[t * 256 + idx] : g_scores[idx * 256 + t];
    __shared__ float sv[256];
    __shared__ int   si[256];
    sv[t] = v; si[t] = t;
    __syncthreads();
    for (int s = 128; s > 0; s >>= 1) {
        if (t < s) {
            if (sv[t + s] > sv[t] || (sv[t + s] == sv[t] && si[t + s] < si[t])) {
                sv[t] = sv[t + s]; si[t] = si[t + s];
            }
        }
        __syncthreads();
    }
    if (t == 0) { if (col) g_idxR[idx] = si[0]; else g_idxL[idx] = si[0]; }
}

// ============================ Kernel C: attribute matching ============================
__global__ __launch_bounds__(256) void attr_kernel(
    const float* __restrict__ L, const float* __restrict__ R,
    const float* __restrict__ AEl, const float* __restrict__ AEr,
    const float* __restrict__ empty,
    const int* __restrict__ lensL, const int* __restrict__ lensR)
{
    const int b = blockIdx.x;
    const int side = b >> 2;
    const int a = b & 3;
    const float* T  = side ? R : L;
    const float* O  = side ? L : R;
    const int*   ix = side ? g_idxR : g_idxL;
    const float* AE = side ? AEr : AEl;
    const int* lens = side ? lensR : lensL;
    const int t = threadIdx.x;

    int start = 0;
    for (int i = 0; i < a; ++i) start += lens[i];
    const int len = lens[a];
    float* rep = g_xent + (size_t)(side * 4 + a) * 768;

    if (len == 0) {
        for (int d = t; d < 768; d += 256) rep[d] = empty[d];
        return;
    }
    __shared__ float sw[256];
    __shared__ float red[256];
    float s = -1e30f;
    if (t < len) {
        float acc = 0.f;
        const float* tok = T + (size_t)(start + t) * 768;
        const float* ae  = AE + (size_t)a * 768;
        for (int d = 0; d < 768; ++d) acc = fmaf(tok[d], ae[d], acc);
        s = acc;
    }
    red[t] = s;
    __syncthreads();
    for (int st = 128; st > 0; st >>= 1) {
        if (t < st) red[t] = fmaxf(red[t], red[t + st]);
        __syncthreads();
    }
    const float m = red[0];
    __syncthreads();
    const float e = (t < len) ? __expf(s - m) : 0.f;
    red[t] = e;
    __syncthreads();
    for (int st = 128; st > 0; st >>= 1) {
        if (t < st) red[t] += red[t + st];
        __syncthreads();
    }
    sw[t] = e / red[0];
    __syncthreads();
    for (int d = t; d < 768; d += 256) {
        float acc = 0.f;
        for (int i = 0; i < len; ++i) {
            const int tok = start + i;
            acc = fmaf(sw[i],
                       fabsf(T[(size_t)tok * 768 + d] - O[(size_t)ix[tok] * 768 + d]), acc);
        }
        rep[d] = acc;
    }
}

// ============================ Kernel D: entity matvec partials ============================
__global__ __launch_bounds__(256) void ent_partial(
    const float* __restrict__ Wn, const float* __restrict__ Wg)
{
    const int j  = blockIdx.x * 256 + threadIdx.x;
    const int rs = blockIdx.y;                      // 0..31
    const int i0 = rs * 192;
    float au = 0.f, av = 0.f;
    #pragma unroll 8
    for (int i = 0; i < 192; ++i) {
        const float xi = g_xent[i0 + i];
        au = fmaf(xi, Wn[(size_t)(i0 + i) * 6144 + j], au);
        av = fmaf(xi, Wg[(size_t)(i0 + i) * 6144 + j], av);
    }
    g_pu[rs * 6144 + j] = au;
    g_pv[rs * 6144 + j] = av;
}

// ============================ Kernel E: finalize ============================
__global__ __launch_bounds__(256) void ent_final(
    const float* __restrict__ bn, const float* __restrict__ bg,
    const float* __restrict__ Wl2, const float* __restrict__ bl2,
    float* __restrict__ out)
{
    const int t = threadIdx.x;
    float l0 = 0.f, l1 = 0.f;
    for (int j = t; j < 6144; j += 256) {
        float u = bn[j], v = bg[j];
        #pragma unroll
        for (int s = 0; s < 32; ++s) { u += g_pu[s * 6144 + j]; v += g_pv[s * 6144 + j]; }
        const float x = g_xent[j];
        const float g = 1.f / (1.f + __expf(-v));
        const float hw = fmaxf(u, 0.f) * g + (1.f - g) * x;
        l0 = fmaf(hw, Wl2[(size_t)j * 2 + 0], l0);
        l1 = fmaf(hw, Wl2[(size_t)j * 2 + 1], l1);
    }
    __shared__ float r0[256], r1[256];
    r0[t] = l0; r1[t] = l1;
    __syncthreads();
    for (int s = 128; s > 0; s >>= 1) {
        if (t < s) { r0[t] += r0[t + s]; r1[t] += r1[t + s]; }
        __syncthreads();
    }
    if (t == 0) {
        const float a = r0[0] + bl2[0];
        const float b = r1[0] + bl2[1];
        const float m = fmaxf(a, b);
        const float ea = __expf(a - m), eb = __expf(b - m);
        const float inv = 1.f / (ea + eb);
        out[0] = ea * inv;
        out[1] = eb * inv;
    }
}

// ============================ launcher ============================
extern "C" void kernel_launch(void* const* d_in, const int* in_sizes, int n_in,
                              void* d_out, int out_size)
{
    const float* left_emb   = (const float*)d_in[0];
    const float* right_emb  = (const float*)d_in[1];
    const float* Wn_tok     = (const float*)d_in[2];
    const float* bn_tok     = (const float*)d_in[3];
    const float* Wg_tok     = (const float*)d_in[4];
    const float* bg_tok     = (const float*)d_in[5];
    const float* W_lin_tok  = (const float*)d_in[6];
    const float* attr_l     = (const float*)d_in[8];
    const float* attr_r     = (const float*)d_in[9];
    const float* Wn_ent     = (const float*)d_in[10];
    const float* bn_ent     = (const float*)d_in[11];
    const float* Wg_ent     = (const float*)d_in[12];
    const float* bg_ent     = (const float*)d_in[13];
    const float* W_lin_ent  = (const float*)d_in[14];
    const float* b_lin_ent  = (const float*)d_in[15];
    const float* empty_attr = (const float*)d_in[16];
    const int*   lensL      = (const int*)d_in[17];
    const int*   lensR      = (const int*)d_in[18];
    float* out = (float*)d_out;

    cudaFuncSetAttribute(score_kernel, cudaFuncAttributeMaxDynamicSharedMemorySize, SMEM_BYTES);

    prep_w<<<576, 256>>>(Wn_tok, Wg_tok);
    score_kernel<<<256, 256, SMEM_BYTES>>>(left_emb, right_emb, bn_tok, bg_tok, W_lin_tok);
    argmax_kernel<<<512, 256>>>();
    attr_kernel<<<8, 256>>>(left_emb, right_emb, attr_l, attr_r,
                            empty_attr, lensL, lensR);
    dim3 gridD(24, 32);
    ent_partial<<<gridD, 256>>>(Wn_ent, Wg_ent);
    ent_final<<<1, 256>>>(bn_ent, bg_ent, W_lin_ent, b_lin_ent, out);
}